// round 1
// baseline (speedup 1.0000x reference)
#include <cuda_runtime.h>

// Problem shape (ParallelScan: B=4, S=4096, D=2048, fp32)
#define BB      4
#define SSEQ    4096
#define DDIM    2048

#define TPB     256          // threads per block
#define VPT     4            // floats per thread (float4)
#define TW      (TPB*VPT)    // 1024 d-columns per block tile
#define DT      (DDIM/TW)    // 2 d-tiles
#define LCH     8            // rows (seq positions) per chunk
#define NCHUNK  (SSEQ/LCH)   // 512 chunks per chain
#define NCHAIN  (BB*DT)      // 8 chains

// Scratch (static device arrays: allocation-free, graph-safe)
__device__ float g_aggA[NCHAIN*NCHUNK*TW];
__device__ float g_aggB[NCHAIN*NCHUNK*TW];
__device__ float g_incA[NCHAIN*NCHUNK*TW];
__device__ float g_incB[NCHAIN*NCHUNK*TW];
__device__ int   g_flags[NCHAIN*NCHUNK];

__global__ void init_flags_kernel() {
    int i = blockIdx.x * blockDim.x + threadIdx.x;
    if (i < NCHAIN*NCHUNK) g_flags[i] = 0;
}

__device__ __forceinline__ float4 f4_fma(float4 a, float4 h, float4 b) {
    return make_float4(fmaf(a.x,h.x,b.x), fmaf(a.y,h.y,b.y),
                       fmaf(a.z,h.z,b.z), fmaf(a.w,h.w,b.w));
}
__device__ __forceinline__ float4 f4_mul(float4 a, float4 b) {
    return make_float4(a.x*b.x, a.y*b.y, a.z*b.z, a.w*b.w);
}

__global__ __launch_bounds__(TPB)
void scan_lookback_kernel(const float* __restrict__ a,
                          const float* __restrict__ b,
                          const float* __restrict__ h0,
                          float* __restrict__ out)
{
    const int chunk = blockIdx.x;        // 0..NCHUNK-1 (fastest varying -> in-order dispatch per chain)
    const int dtile = blockIdx.y;        // 0..DT-1
    const int batch = blockIdx.z;        // 0..BB-1
    const int chain = batch * DT + dtile;
    const int col   = dtile * TW + threadIdx.x * VPT;
    const int s0    = chunk * LCH;
    const size_t base = ((size_t)batch * SSEQ + s0) * DDIM + col;

    // ---- Phase 1: load chunk into registers (independent loads -> high MLP) ----
    float4 ra[LCH], rb[LCH];
#pragma unroll
    for (int i = 0; i < LCH; i++) {
        ra[i] = *(const float4*)(a + base + (size_t)i * DDIM);
        rb[i] = *(const float4*)(b + base + (size_t)i * DDIM);
    }

    if (chunk == 0) {
        // fold h0 into first input: b0 += a0 * h0
        float4 h = *(const float4*)(h0 + (size_t)batch * DDIM + col);
        rb[0] = f4_fma(ra[0], h, rb[0]);
    }

    // ---- Local chunk composition: (A, B) = compose of LCH elements ----
    float4 Aagg = make_float4(1.f,1.f,1.f,1.f);
    float4 Bagg = make_float4(0.f,0.f,0.f,0.f);
#pragma unroll
    for (int i = 0; i < LCH; i++) {
        Bagg = f4_fma(ra[i], Bagg, rb[i]);
        Aagg = f4_mul(Aagg, ra[i]);
    }

    const int slot  = chain * NCHUNK + chunk;
    const int cbase = slot * TW + threadIdx.x * VPT;

    float4 excA, excB;   // exclusive prefix (composition of chunks 0..chunk-1)

    if (chunk == 0) {
        excA = make_float4(1.f,1.f,1.f,1.f);
        excB = make_float4(0.f,0.f,0.f,0.f);
        // inclusive == local
        *(float4*)(g_incA + cbase) = Aagg;
        *(float4*)(g_incB + cbase) = Bagg;
        __threadfence();
        __syncthreads();
        if (threadIdx.x == 0) atomicExch(&g_flags[slot], 2);
    } else {
        // publish aggregate (flag = 1) so successors can look past us
        *(float4*)(g_aggA + cbase) = Aagg;
        *(float4*)(g_aggB + cbase) = Bagg;
        __threadfence();
        __syncthreads();
        if (threadIdx.x == 0) atomicExch(&g_flags[slot], 1);

        // ---- Decoupled lookback (per-thread, elementwise columns) ----
        float4 RA = make_float4(1.f,1.f,1.f,1.f);   // composition of chunks (p+1 .. chunk-1)
        float4 RB = make_float4(0.f,0.f,0.f,0.f);
        int p = chunk - 1;
        for (;;) {
            const int pslot = chain * NCHUNK + p;
            int f;
            do { f = *((volatile int*)&g_flags[pslot]); } while (f == 0);
            __threadfence();   // acquire: order flag load before data loads
            const int pb = pslot * TW + threadIdx.x * VPT;
            if (f == 2) {
                float4 PA = *(const float4*)(g_incA + pb);
                float4 PB = *(const float4*)(g_incB + pb);
                // exc = combine(inclusive_p, R): (Al*Ar, Ar*Bl + Br)
                excA = f4_mul(PA, RA);
                excB = f4_fma(RA, PB, RB);
                break;
            } else {
                float4 PA = *(const float4*)(g_aggA + pb);
                float4 PB = *(const float4*)(g_aggB + pb);
                // R = combine(agg_p, R)
                RB = f4_fma(RA, PB, RB);
                RA = f4_mul(PA, RA);
                p--;
            }
        }

        // inclusive = combine(exc, local)
        float4 IA = f4_mul(excA, Aagg);
        float4 IB = f4_fma(Aagg, excB, Bagg);
        *(float4*)(g_incA + cbase) = IA;
        *(float4*)(g_incB + cbase) = IB;
        __threadfence();
        __syncthreads();
        if (threadIdx.x == 0) atomicExch(&g_flags[slot], 2);
    }

    // ---- Phase 2: replay recurrence from registers with entry state, write out ----
    float4 h = excB;
#pragma unroll
    for (int i = 0; i < LCH; i++) {
        h = f4_fma(ra[i], h, rb[i]);
        *(float4*)(out + base + (size_t)i * DDIM) = h;
    }
}

extern "C" void kernel_launch(void* const* d_in, const int* in_sizes, int n_in,
                              void* d_out, int out_size)
{
    const float* a  = (const float*)d_in[0];
    const float* b  = (const float*)d_in[1];
    const float* h0 = (const float*)d_in[2];
    float* out = (float*)d_out;

    init_flags_kernel<<<(NCHAIN*NCHUNK + 255)/256, 256>>>();

    dim3 grid(NCHUNK, DT, BB);
    scan_lookback_kernel<<<grid, TPB>>>(a, b, h0, out);
}

// round 6
// speedup vs baseline: 2.5435x; 2.5435x over previous
#include <cuda_runtime.h>

// Problem shape (ParallelScan: B=4, S=4096, D=2048, fp32)
#define BB      4
#define SSEQ    4096
#define DDIM    2048

#define TPB     256          // threads per block
#define VPT     4            // floats per thread (float4)
#define TW      (TPB*VPT)    // 1024 d-columns per block tile
#define DT      (DDIM/TW)    // 2 d-tiles
#define LCH     32           // rows (seq positions) per chunk
#define NCHUNK  (SSEQ/LCH)   // 128 chunks per chain
#define NCHAIN  (BB*DT)      // 8 chains

// Scratch: chunk compositions / exclusive prefixes (4 MB each). Allocation-free.
__device__ float g_aggA[NCHAIN*NCHUNK*TW];
__device__ float g_aggB[NCHAIN*NCHUNK*TW];

__device__ __forceinline__ float4 f4_fma(float4 a, float4 h, float4 b) {
    return make_float4(fmaf(a.x,h.x,b.x), fmaf(a.y,h.y,b.y),
                       fmaf(a.z,h.z,b.z), fmaf(a.w,h.w,b.w));
}
__device__ __forceinline__ float4 f4_mul(float4 a, float4 b) {
    return make_float4(a.x*b.x, a.y*b.y, a.z*b.z, a.w*b.w);
}

// ---------------- K1: per-chunk composition (A, B), pure streaming ----------------
__global__ __launch_bounds__(TPB)
void k1_aggregate(const float* __restrict__ a,
                  const float* __restrict__ b,
                  const float* __restrict__ h0)
{
    const int chunk = blockIdx.x;
    const int dtile = blockIdx.y;
    const int batch = blockIdx.z;
    const int chain = batch * DT + dtile;
    const int col   = dtile * TW + threadIdx.x * VPT;
    const size_t base = ((size_t)batch * SSEQ + (size_t)chunk * LCH) * DDIM + col;

    float4 A  = make_float4(1.f,1.f,1.f,1.f);
    float4 Bc = make_float4(0.f,0.f,0.f,0.f);

    if (chunk == 0) {
        // fold h0 into the first element: b0' = b0 + a0*h0
        // (the aggregate chain then carries the h0 contribution to all chunks >= 1)
        float4 h  = *(const float4*)(h0 + (size_t)batch * DDIM + col);
        float4 a0 = *(const float4*)(a + base);
        float4 b0 = *(const float4*)(b + base);
        Bc = f4_fma(a0, h, b0);
        A  = a0;
#pragma unroll 4
        for (int i = 1; i < LCH; i++) {
            float4 ra = *(const float4*)(a + base + (size_t)i * DDIM);
            float4 rb = *(const float4*)(b + base + (size_t)i * DDIM);
            Bc = f4_fma(ra, Bc, rb);
            A  = f4_mul(A, ra);
        }
    } else {
#pragma unroll 4
        for (int i = 0; i < LCH; i++) {
            float4 ra = *(const float4*)(a + base + (size_t)i * DDIM);
            float4 rb = *(const float4*)(b + base + (size_t)i * DDIM);
            Bc = f4_fma(ra, Bc, rb);
            A  = f4_mul(A, ra);
        }
    }

    const int slot = (chain * NCHUNK + chunk) * TW + threadIdx.x * VPT;
    *(float4*)(g_aggA + slot) = A;
    *(float4*)(g_aggB + slot) = Bc;
}

// ---------------- K2: serial scan over chunk aggregates -> exclusive prefixes ----
// After K2, g_aggB[chain][k][col] holds the state ENTERING chunk k (excB),
// i.e. the true hidden state h_{k*LCH-1} (h0 contribution included via chunk 0's
// folded aggregate). excA is never consumed downstream, so it is not written back.
__global__ __launch_bounds__(TPB)
void k2_scan_aggregates()
{
    const int dtile = blockIdx.x;
    const int batch = blockIdx.y;
    const int chain = batch * DT + dtile;
    const int coff  = threadIdx.x * VPT;

    float4 cB = make_float4(0.f,0.f,0.f,0.f);

    const int base = chain * NCHUNK * TW + coff;

#pragma unroll 4
    for (int k = 0; k < NCHUNK; k++) {
        const int s = base + k * TW;
        float4 gA = *(const float4*)(g_aggA + s);
        float4 gB = *(const float4*)(g_aggB + s);
        // write exclusive prefix (entry state) in place
        *(float4*)(g_aggB + s) = cB;
        // carry = combine(carry, agg):  B = gA*cB + gB
        cB = f4_fma(gA, cB, gB);
    }
}

// ---------------- K3: replay recurrence with entry state, write output ----------
__global__ __launch_bounds__(TPB)
void k3_apply(const float* __restrict__ a,
              const float* __restrict__ b,
              const float* __restrict__ h0,
              float* __restrict__ out)
{
    const int chunk = blockIdx.x;
    const int dtile = blockIdx.y;
    const int batch = blockIdx.z;
    const int chain = batch * DT + dtile;
    const int col   = dtile * TW + threadIdx.x * VPT;
    const size_t base = ((size_t)batch * SSEQ + (size_t)chunk * LCH) * DDIM + col;

    // Entry state. K3 replays from RAW b, so:
    //   chunk 0:    true entry state is h0 (excB there is 0 and b0 is unfolded)
    //   chunk >= 1: excB already equals the true h at chunk entry
    float4 h;
    if (chunk == 0) {
        h = *(const float4*)(h0 + (size_t)batch * DDIM + col);
    } else {
        const int slot = (chain * NCHUNK + chunk) * TW + threadIdx.x * VPT;
        h = *(const float4*)(g_aggB + slot);
    }

#pragma unroll 4
    for (int i = 0; i < LCH; i++) {
        float4 ra = *(const float4*)(a + base + (size_t)i * DDIM);
        float4 rb = *(const float4*)(b + base + (size_t)i * DDIM);
        h = f4_fma(ra, h, rb);
        *(float4*)(out + base + (size_t)i * DDIM) = h;
    }
}

extern "C" void kernel_launch(void* const* d_in, const int* in_sizes, int n_in,
                              void* d_out, int out_size)
{
    const float* a  = (const float*)d_in[0];
    const float* b  = (const float*)d_in[1];
    const float* h0 = (const float*)d_in[2];
    float* out = (float*)d_out;

    dim3 g1(NCHUNK, DT, BB);
    k1_aggregate<<<g1, TPB>>>(a, b, h0);

    dim3 g2(DT, BB);
    k2_scan_aggregates<<<g2, TPB>>>();

    dim3 g3(NCHUNK, DT, BB);
    k3_apply<<<g3, TPB>>>(a, b, h0, out);
}

// round 7
// speedup vs baseline: 3.0115x; 1.1840x over previous
#include <cuda_runtime.h>

// Problem shape (ParallelScan: B=4, S=4096, D=2048, fp32)
#define BB      4
#define SSEQ    4096
#define DDIM    2048

#define TPB     256          // threads per block (K1/K3)
#define VPT     4            // floats per thread (float4)
#define TW      (TPB*VPT)    // 1024 d-columns per block tile
#define DT      (DDIM/TW)    // 2 d-tiles
#define LCH     64           // rows (seq positions) per chunk -> 512 blocks = single wave
#define NCHUNK  (SSEQ/LCH)   // 64 chunks per chain
#define NCHAIN  (BB*DT)      // 8 chains

// K2 decomposition: 2048 independent serial columns spread over 64 warps
#define K2_SPLIT   8                     // blocks per chain
#define K2_TPB     32                    // one warp per block
#define K2_COLS    (TW / VPT / K2_SPLIT) // 32 float4-columns per block (== K2_TPB)

// Scratch: chunk compositions / exclusive prefixes (2 MB each -> L2-resident).
__device__ float g_aggA[NCHAIN*NCHUNK*TW];
__device__ float g_aggB[NCHAIN*NCHUNK*TW];

__device__ __forceinline__ float4 f4_fma(float4 a, float4 h, float4 b) {
    return make_float4(fmaf(a.x,h.x,b.x), fmaf(a.y,h.y,b.y),
                       fmaf(a.z,h.z,b.z), fmaf(a.w,h.w,b.w));
}
__device__ __forceinline__ float4 f4_mul(float4 a, float4 b) {
    return make_float4(a.x*b.x, a.y*b.y, a.z*b.z, a.w*b.w);
}

// ---------------- K1: per-chunk composition (A, B), pure streaming ----------------
__global__ __launch_bounds__(TPB)
void k1_aggregate(const float* __restrict__ a,
                  const float* __restrict__ b,
                  const float* __restrict__ h0)
{
    const int chunk = blockIdx.x;
    const int dtile = blockIdx.y;
    const int batch = blockIdx.z;
    const int chain = batch * DT + dtile;
    const int col   = dtile * TW + threadIdx.x * VPT;
    const size_t base = ((size_t)batch * SSEQ + (size_t)chunk * LCH) * DDIM + col;

    float4 A  = make_float4(1.f,1.f,1.f,1.f);
    float4 Bc = make_float4(0.f,0.f,0.f,0.f);

    if (chunk == 0) {
        // fold h0 into the first element: b0' = b0 + a0*h0
        // (the aggregate chain then carries the h0 contribution to all chunks >= 1)
        float4 h  = *(const float4*)(h0 + (size_t)batch * DDIM + col);
        float4 a0 = *(const float4*)(a + base);
        float4 b0 = *(const float4*)(b + base);
        Bc = f4_fma(a0, h, b0);
        A  = a0;
#pragma unroll 4
        for (int i = 1; i < LCH; i++) {
            float4 ra = *(const float4*)(a + base + (size_t)i * DDIM);
            float4 rb = *(const float4*)(b + base + (size_t)i * DDIM);
            Bc = f4_fma(ra, Bc, rb);
            A  = f4_mul(A, ra);
        }
    } else {
#pragma unroll 4
        for (int i = 0; i < LCH; i++) {
            float4 ra = *(const float4*)(a + base + (size_t)i * DDIM);
            float4 rb = *(const float4*)(b + base + (size_t)i * DDIM);
            Bc = f4_fma(ra, Bc, rb);
            A  = f4_mul(A, ra);
        }
    }

    const int slot = (chain * NCHUNK + chunk) * TW + threadIdx.x * VPT;
    *(float4*)(g_aggA + slot) = A;
    *(float4*)(g_aggB + slot) = Bc;
}

// ---------------- K2: serial scan over chunk aggregates -> exclusive prefixes ----
// 64 one-warp blocks; each thread owns one independent float4 column and scans
// NCHUNK=64 aggregates serially with +1 software prefetch to hide L2 latency.
// After K2, g_aggB[chain][k][col] = state ENTERING chunk k (excB).
__global__ __launch_bounds__(K2_TPB)
void k2_scan_aggregates()
{
    const int chain = blockIdx.x / K2_SPLIT;
    const int part  = blockIdx.x % K2_SPLIT;
    const int coff  = (part * K2_COLS + threadIdx.x) * VPT;

    const int base = chain * NCHUNK * TW + coff;

    float4 cB = make_float4(0.f,0.f,0.f,0.f);

    int s = base;
    float4 gA = *(const float4*)(g_aggA + s);
    float4 gB = *(const float4*)(g_aggB + s);

#pragma unroll 4
    for (int k = 0; k < NCHUNK; k++) {
        const int s2 = s + TW;
        float4 nA, nB;
        if (k + 1 < NCHUNK) {
            nA = *(const float4*)(g_aggA + s2);   // prefetch next chunk's aggregate
            nB = *(const float4*)(g_aggB + s2);
        }
        *(float4*)(g_aggB + s) = cB;              // exclusive prefix in place
        cB = f4_fma(gA, cB, gB);                  // carry = gA*carry + gB
        gA = nA; gB = nB; s = s2;
    }
}

// ---------------- K3: replay recurrence with entry state, write output ----------
__global__ __launch_bounds__(TPB)
void k3_apply(const float* __restrict__ a,
              const float* __restrict__ b,
              const float* __restrict__ h0,
              float* __restrict__ out)
{
    const int chunk = blockIdx.x;
    const int dtile = blockIdx.y;
    const int batch = blockIdx.z;
    const int chain = batch * DT + dtile;
    const int col   = dtile * TW + threadIdx.x * VPT;
    const size_t base = ((size_t)batch * SSEQ + (size_t)chunk * LCH) * DDIM + col;

    // Entry state. K3 replays from RAW b, so:
    //   chunk 0:    true entry state is h0 (excB there is 0 and b0 is unfolded)
    //   chunk >= 1: excB already equals the true h at chunk entry
    float4 h;
    if (chunk == 0) {
        h = *(const float4*)(h0 + (size_t)batch * DDIM + col);
    } else {
        const int slot = (chain * NCHUNK + chunk) * TW + threadIdx.x * VPT;
        h = *(const float4*)(g_aggB + slot);
    }

#pragma unroll 4
    for (int i = 0; i < LCH; i++) {
        float4 ra = *(const float4*)(a + base + (size_t)i * DDIM);
        float4 rb = *(const float4*)(b + base + (size_t)i * DDIM);
        h = f4_fma(ra, h, rb);
        *(float4*)(out + base + (size_t)i * DDIM) = h;
    }
}

extern "C" void kernel_launch(void* const* d_in, const int* in_sizes, int n_in,
                              void* d_out, int out_size)
{
    const float* a  = (const float*)d_in[0];
    const float* b  = (const float*)d_in[1];
    const float* h0 = (const float*)d_in[2];
    float* out = (float*)d_out;

    dim3 g1(NCHUNK, DT, BB);
    k1_aggregate<<<g1, TPB>>>(a, b, h0);

    k2_scan_aggregates<<<NCHAIN * K2_SPLIT, K2_TPB>>>();

    dim3 g3(NCHUNK, DT, BB);
    k3_apply<<<g3, TPB>>>(a, b, h0, out);
}